// round 7
// baseline (speedup 1.0000x reference)
#include <cuda_runtime.h>
#include <cuda_fp16.h>
#include <cstdint>

#define N_NODES_MAX 100000
#define D_FEAT 128

// Scratch (static __device__ arrays — no allocation per harness rules)
__device__ float  g_pos[N_NODES_MAX];    // exact fp32 pos (for output col 0)
__device__ __half g_posh[N_NODES_MAX];   // fp16 pos copy: 200KB, L1-resident for gathers
__device__ float2 g_acc[N_NODES_MAX];    // {sum_dist, count}

// Kernel 1: compact pos column (fp32 + fp16 copies) + zero accumulators.
// At DRAM row-activation floor (~6us) — stride-512B column read touches every
// row of the 51.2MB tensor; cost ~= streaming the whole array.
__global__ void k_init(const float* __restrict__ h, int n_nodes) {
    int i = blockIdx.x * blockDim.x + threadIdx.x;
    if (i < n_nodes) {
        float v = h[(size_t)i * D_FEAT];
        g_pos[i]  = v;
        g_posh[i] = __float2half(v);
        g_acc[i]  = make_float2(0.0f, 0.0f);
    }
}

__device__ __forceinline__ void edge_accum(int s, int d) {
    float ps = __half2float(g_posh[s]);
    float pd = __half2float(g_posh[d]);
    float dist = fabsf(ps - pd);
    float2* p = &g_acc[d];
    asm volatile("red.global.add.v2.f32 [%0], {%1, %2};"
                 :: "l"(p), "f"(dist), "f"(1.0f) : "memory");
}

// Streaming (evict-first) int4 load: keeps the 51.2MB index stream from
// evicting the 200KB fp16 pos table out of L1.
__device__ __forceinline__ int4 ldcs_int4(const int* p) {
    int4 v;
    asm volatile("ld.global.cs.v4.s32 {%0,%1,%2,%3}, [%4];"
                 : "=r"(v.x), "=r"(v.y), "=r"(v.z), "=r"(v.w)
                 : "l"(p));
    return v;
}

// Kernel 2: edge scatter. 16 edges/thread via 4x int4 streaming loads per
// index array (MLP=8 up front), then 16 gathers + 16 red.v2 atomics.
// Chip floor: REDG structural 4cyc/SMSP => ~21us for 6.4M atomics.
__global__ void k_edges(const int* __restrict__ src,
                        const int* __restrict__ dst,
                        int n_edges) {
    int t = blockIdx.x * blockDim.x + threadIdx.x;
    int e0 = t * 16;
    if (e0 + 15 < n_edges) {
        int4 s[4], d[4];
#pragma unroll
        for (int j = 0; j < 4; j++) s[j] = ldcs_int4(src + e0 + 4 * j);
#pragma unroll
        for (int j = 0; j < 4; j++) d[j] = ldcs_int4(dst + e0 + 4 * j);
#pragma unroll
        for (int j = 0; j < 4; j++) {
            edge_accum(s[j].x, d[j].x);
            edge_accum(s[j].y, d[j].y);
            edge_accum(s[j].z, d[j].z);
            edge_accum(s[j].w, d[j].w);
        }
    } else if (e0 < n_edges) {
        for (int e = e0; e < n_edges; e++)
            edge_accum(src[e], dst[e]);
    }
}

// Kernel 3: finalize output (N, 2): col0 = exact fp32 pos, col1 = sum/max(cnt,1)
__global__ void k_final(float* __restrict__ out, int n_nodes) {
    int i = blockIdx.x * blockDim.x + threadIdx.x;
    if (i < n_nodes) {
        float2 a = g_acc[i];
        float2 r = make_float2(g_pos[i], a.x / fmaxf(a.y, 1.0f));
        *reinterpret_cast<float2*>(out + 2 * (size_t)i) = r;
    }
}

extern "C" void kernel_launch(void* const* d_in, const int* in_sizes, int n_in,
                              void* d_out, int out_size) {
    const float* h   = (const float*)d_in[0];
    const int*   src = (const int*)d_in[1];
    const int*   dst = (const int*)d_in[2];
    float* out = (float*)d_out;

    int n_nodes = in_sizes[0] / D_FEAT;
    int n_edges = in_sizes[1];

    const int TPB = 256;
    int init_blocks = (n_nodes + TPB - 1) / TPB;
    k_init<<<init_blocks, TPB>>>(h, n_nodes);

    int n_chunks = (n_edges + 15) / 16;
    int edge_blocks = (n_chunks + TPB - 1) / TPB;
    k_edges<<<edge_blocks, TPB>>>(src, dst, n_edges);

    k_final<<<init_blocks, TPB>>>(out, n_nodes);
}

// round 10
// speedup vs baseline: 1.0043x; 1.0043x over previous
#include <cuda_runtime.h>
#include <cuda_fp16.h>
#include <cstdint>

#define N_NODES_MAX 100000
#define D_FEAT 128

// Fixed-point packing: one u64 atomic carries both sum and count.
//   low 40 bits:  sum of dist in 2^-20 units  (dist<=~10 -> <=1e7/edge; x1000 deg << 2^40)
//   high bits:    edge count (+= 1<<40 per edge)
#define FP_SCALE   1048576.0f          // 2^20
#define FP_INV     (1.0f/1048576.0f)
#define CNT_ONE    (1ULL << 40)
#define SUM_MASK   ((1ULL << 40) - 1)

// Scratch (static __device__ arrays — no allocation per harness rules)
__device__ float              g_pos[N_NODES_MAX];   // exact fp32 pos (output col 0)
__device__ __half             g_posh[N_NODES_MAX];  // fp16 pos: 200KB, L1-resident gathers
__device__ unsigned long long g_acc[N_NODES_MAX];   // packed {cnt:24, sum_fx:40}

// Kernel 1: compact pos column + zero accumulators. At DRAM row-activation
// floor (~6us): stride-512B column read touches every row of the 51.2MB tensor.
__global__ void k_init(const float* __restrict__ h, int n_nodes) {
    int i = blockIdx.x * blockDim.x + threadIdx.x;
    if (i < n_nodes) {
        float v = h[(size_t)i * D_FEAT];
        g_pos[i]  = v;
        g_posh[i] = __float2half(v);
        g_acc[i]  = 0ULL;
    }
}

__device__ __forceinline__ void edge_accum(int s, int d) {
    float ps = __half2float(g_posh[s]);
    float pd = __half2float(g_posh[d]);
    float dist = fabsf(ps - pd);
    unsigned long long v = __float2ull_rn(dist * FP_SCALE) + CNT_ONE;
    asm volatile("red.global.add.u64 [%0], %1;"
                 :: "l"(&g_acc[d]), "l"(v) : "memory");
}

// Kernel 2: edge scatter. 8 edges/thread (R5 structure — 16/thread regressed),
// one u64 integer reduction per edge (half the LTS-ALU ops of red.v2.f32).
__global__ void k_edges(const int* __restrict__ src,
                        const int* __restrict__ dst,
                        int n_edges) {
    int t = blockIdx.x * blockDim.x + threadIdx.x;
    int e0 = t * 8;
    if (e0 + 7 < n_edges) {
        int4 s0 = *reinterpret_cast<const int4*>(src + e0);
        int4 s1 = *reinterpret_cast<const int4*>(src + e0 + 4);
        int4 d0 = *reinterpret_cast<const int4*>(dst + e0);
        int4 d1 = *reinterpret_cast<const int4*>(dst + e0 + 4);
        edge_accum(s0.x, d0.x);
        edge_accum(s0.y, d0.y);
        edge_accum(s0.z, d0.z);
        edge_accum(s0.w, d0.w);
        edge_accum(s1.x, d1.x);
        edge_accum(s1.y, d1.y);
        edge_accum(s1.z, d1.z);
        edge_accum(s1.w, d1.w);
    } else if (e0 < n_edges) {
        for (int e = e0; e < n_edges; e++)
            edge_accum(src[e], dst[e]);
    }
}

// Kernel 3: finalize (N,2): col0 = exact fp32 pos, col1 = sum/max(cnt,1)
__global__ void k_final(float* __restrict__ out, int n_nodes) {
    int i = blockIdx.x * blockDim.x + threadIdx.x;
    if (i < n_nodes) {
        unsigned long long v = g_acc[i];
        float cnt = (float)(v >> 40);
        float sum = (float)(v & SUM_MASK) * FP_INV;
        float2 r = make_float2(g_pos[i], sum / fmaxf(cnt, 1.0f));
        *reinterpret_cast<float2*>(out + 2 * (size_t)i) = r;
    }
}

extern "C" void kernel_launch(void* const* d_in, const int* in_sizes, int n_in,
                              void* d_out, int out_size) {
    const float* h   = (const float*)d_in[0];
    const int*   src = (const int*)d_in[1];
    const int*   dst = (const int*)d_in[2];
    float* out = (float*)d_out;

    int n_nodes = in_sizes[0] / D_FEAT;
    int n_edges = in_sizes[1];

    const int TPB = 256;
    int init_blocks = (n_nodes + TPB - 1) / TPB;
    k_init<<<init_blocks, TPB>>>(h, n_nodes);

    int n_oct = (n_edges + 7) / 8;
    int edge_blocks = (n_oct + TPB - 1) / TPB;
    k_edges<<<edge_blocks, TPB>>>(src, dst, n_edges);

    k_final<<<init_blocks, TPB>>>(out, n_nodes);
}